// round 11
// baseline (speedup 1.0000x reference)
#include <cuda_runtime.h>
#include <cuda_fp16.h>
#include <stdint.h>

#define Bsz 4
#define Sq  4096
#define Dd  1024
#define BS  (Bsz * Sq)   // 16384

// ---------------- scratch (device globals — allocation is forbidden) ----------------
__device__ __align__(256) __half g_xh[(long long)BS * Dd];
__device__ __align__(256) __half g_WkTs[Dd * Dd];
__device__ __align__(256) __half g_WvTs[Dd * Dd];
__device__ __align__(256) __half g_Kh[(long long)BS * Dd];
__device__ __align__(256) __half g_Vh[(long long)BS * Dd];
__device__ __align__(256) float  g_S[Bsz * 513 * 2];
__device__ __align__(256) float  g_s[Bsz * Dd];
__device__ __align__(256) float  g_r[Bsz * Dd];
__device__ __align__(256) __half g_W2tmp[(long long)Bsz * Dd * Dd];  // [b][d][n]
__device__ __align__(256) __half g_W2Ts[(long long)Bsz * Dd * Dd];   // [b][n][d]

// ---------------- PTX helpers ----------------
__device__ __forceinline__ uint32_t smem_u32(const void* p) {
    uint32_t a;
    asm("{ .reg .u64 t; cvta.to.shared.u64 t, %1; cvt.u32.u64 %0, t; }" : "=r"(a) : "l"(p));
    return a;
}
__device__ __forceinline__ void cp16(uint32_t dst, const void* src) {
    asm volatile("cp.async.cg.shared.global [%0], [%1], 16;" :: "r"(dst), "l"(src));
}
__device__ __forceinline__ void cp_commit() { asm volatile("cp.async.commit_group;" ::: "memory"); }
template<int N> __device__ __forceinline__ void cp_wait() {
    asm volatile("cp.async.wait_group %0;" :: "n"(N) : "memory");
}

__device__ __forceinline__ void ldsm_x4(uint32_t& r0, uint32_t& r1, uint32_t& r2, uint32_t& r3,
                                        uint32_t addr) {
    asm volatile("ldmatrix.sync.aligned.m8n8.x4.shared.b16 {%0,%1,%2,%3}, [%4];"
                 : "=r"(r0), "=r"(r1), "=r"(r2), "=r"(r3) : "r"(addr));
}
__device__ __forceinline__ void mma_fp16(float& c0, float& c1, float& c2, float& c3,
                                         uint32_t a0, uint32_t a1, uint32_t a2, uint32_t a3,
                                         uint32_t b0, uint32_t b1) {
    asm volatile(
        "mma.sync.aligned.m16n8k16.row.col.f32.f16.f16.f32 "
        "{%0,%1,%2,%3}, {%4,%5,%6,%7}, {%8,%9}, {%0,%1,%2,%3};"
        : "+f"(c0), "+f"(c1), "+f"(c2), "+f"(c3)
        : "r"(a0), "r"(a1), "r"(a2), "r"(a3), "r"(b0), "r"(b1));
}

// ---------------- fp16 HMMA GEMM: C[M,N] = Ah @ Bs^T (+bias[n]) ----------------
// CTA tile 128x128x64, 128 threads = 4 warps (2x2), warp tile 64x64, 2 CTAs/SM.
// 3-stage cp.async pipeline. SMEM row = 128B; chunk c at slot c ^ (row & 7).
#define STG1 32768
#define DSMEM1 (3 * STG1)     // 98304

__global__ __launch_bounds__(128, 2) void gemm_hmma(
    const __half* __restrict__ Ah,
    const __half* __restrict__ Bs,
    const float* __restrict__ bias, float* __restrict__ Cf,
    __half* __restrict__ Ch,
    int N, int Ktot,
    long long sA, long long sB, long long sBias, long long sC)
{
    extern __shared__ __align__(128) char smem[];
    const int tid = threadIdx.x;
    const int wid = tid >> 5, lid = tid & 31;
    const int bz = blockIdx.z;
    const long long bm = (long long)blockIdx.y * 128;
    const long long bn = (long long)blockIdx.x * 128;

    const __half* gA0 = Ah + bz * sA + bm * Ktot;
    const __half* gB = Bs + bz * sB + bn * Ktot;
    const float* biasp = bias ? bias + bz * sBias : nullptr;

    const uint32_t sb = smem_u32(smem);
    const int wm = (wid & 1) * 64;
    const int wn = (wid >> 1) * 64;

    float acc[4][8][4];
    #pragma unroll
    for (int a = 0; a < 4; a++)
        #pragma unroll
        for (int b = 0; b < 8; b++)
            #pragma unroll
            for (int c = 0; c < 4; c++) acc[a][b][c] = 0.f;

    auto load_chunk = [&](int slot, int k0) {
        const uint32_t buf = sb + slot * STG1;
        #pragma unroll
        for (int it = 0; it < 8; it++) {
            int id = tid + it * 128;
            int r = id >> 3, c = id & 7;
            cp16(buf + r * 128 + (((c ^ r) & 7) << 4),
                 gA0 + (long long)r * Ktot + k0 + c * 8);
        }
        #pragma unroll
        for (int it = 0; it < 8; it++) {
            int id = tid + it * 128;
            int r = id >> 3, c = id & 7;
            cp16(buf + 16384 + r * 128 + ((c ^ (r & 7)) << 4),
                 gB + (long long)r * Ktot + k0 + c * 8);
        }
        cp_commit();
    };

    const int nc = Ktot >> 6;        // 16
    load_chunk(0, 0);
    load_chunk(1, 64);

    const int a_row = wm + (lid & 15);
    const int a_hi  = lid >> 4;
    const int b_row = wn + (lid & 7) + ((lid >> 4) & 1) * 8;
    const int b_hi  = (lid >> 3) & 1;

    int slot = 0;
    for (int i = 0; i < nc; i++) {
        if (i + 2 < nc) {
            int ns = slot + 2; if (ns >= 3) ns -= 3;
            load_chunk(ns, (i + 2) << 6);
            cp_wait<2>();
        } else if (i + 1 < nc) {
            cp_wait<1>();
        } else {
            cp_wait<0>();
        }
        __syncthreads();

        const uint32_t buf = sb + slot * STG1;
        #pragma unroll
        for (int kk = 0; kk < 4; kk++) {
            uint32_t Af0[4][4];
            #pragma unroll
            for (int mb = 0; mb < 4; mb++) {
                int r = a_row + mb * 16;
                int c = kk * 2 + a_hi;
                ldsm_x4(Af0[mb][0], Af0[mb][1], Af0[mb][2], Af0[mb][3],
                        buf + r * 128 + ((c ^ (r & 7)) << 4));
            }
            uint32_t Bf[4][4];
            #pragma unroll
            for (int nq = 0; nq < 4; nq++) {
                int r = b_row + nq * 16;
                int c = kk * 2 + b_hi;
                ldsm_x4(Bf[nq][0], Bf[nq][1], Bf[nq][2], Bf[nq][3],
                        buf + 16384 + r * 128 + ((c ^ (r & 7)) << 4));
            }
            #pragma unroll
            for (int mb = 0; mb < 4; mb++)
                #pragma unroll
                for (int nq = 0; nq < 4; nq++)
                    #pragma unroll
                    for (int half = 0; half < 2; half++) {
                        float* c = acc[mb][nq * 2 + half];
                        mma_fp16(c[0], c[1], c[2], c[3],
                                 Af0[mb][0], Af0[mb][1], Af0[mb][2], Af0[mb][3],
                                 Bf[nq][half * 2], Bf[nq][half * 2 + 1]);
                    }
        }
        __syncthreads();
        if (++slot == 3) slot = 0;
    }

    const int er = lid >> 2;
    const int ec = (lid & 3) * 2;
    #pragma unroll
    for (int mb = 0; mb < 4; mb++) {
        #pragma unroll
        for (int nb = 0; nb < 8; nb++) {
            const float* c = acc[mb][nb];
            long long col = bn + wn + nb * 8 + ec;
            float bx = 0.f, by = 0.f;
            if (biasp) { bx = biasp[col]; by = biasp[col + 1]; }
            long long r0 = bm + wm + mb * 16 + er;
            float v0 = c[0] + bx, v1 = c[1] + by;
            float v2 = c[2] + bx, v3 = c[3] + by;
            if (Cf) {
                float* Cb = Cf + bz * sC;
                *reinterpret_cast<float2*>(Cb + r0 * N + col) = make_float2(v0, v1);
                *reinterpret_cast<float2*>(Cb + (r0 + 8) * N + col) = make_float2(v2, v3);
            } else {
                __half2 s0 = { __float2half(v0), __float2half(v1) };
                __half2 s1 = { __float2half(v2), __float2half(v3) };
                __half* Hb = Ch + bz * sC;
                *reinterpret_cast<__half2*>(Hb + r0 * N + col) = s0;
                *reinterpret_cast<__half2*>(Hb + (r0 + 8) * N + col) = s1;
            }
        }
    }
}

// ---------------- FFT machinery (radix-4 Stockham, N=1024, 256 threads) ----------------
#define FPAD(i) ((i) + ((i) >> 5))

// one array-set version (used by irfft_s / fft_w2)
__device__ __forceinline__ void fft1024_stages(
    float* br0, float* bi0, float* br1, float* bi1,
    const float* twr, const float* twi, int tid, int inv)
{
    float *sr = br0, *si = bi0, *dr = br1, *di = bi1;
    const int Ls[5] = {256, 64, 16, 4, 1};
    const int Ms[5] = {1, 4, 16, 64, 256};
    #pragma unroll
    for (int st = 0; st < 5; st++) {
        const int l = Ls[st], m = Ms[st];
        int j = tid / m, k = tid - j * m;
        int ti = j * (256 / l);
        float w1r = twr[ti], w1i = twi[ti];
        float w2r = w1r * w1r - w1i * w1i, w2i = 2.f * w1r * w1i;
        float w3r = w2r * w1r - w2i * w1i, w3i = w2r * w1i + w2i * w1r;
        int i0 = k + m * j;
        float c0r = sr[FPAD(i0)],             c0i = si[FPAD(i0)];
        float c1r = sr[FPAD(i0 + m * l)],     c1i = si[FPAD(i0 + m * l)];
        float c2r = sr[FPAD(i0 + 2 * m * l)], c2i = si[FPAD(i0 + 2 * m * l)];
        float c3r = sr[FPAD(i0 + 3 * m * l)], c3i = si[FPAD(i0 + 3 * m * l)];
        float t0r = c0r + c2r, t0i = c0i + c2i;
        float t1r = c0r - c2r, t1i = c0i - c2i;
        float t2r = c1r + c3r, t2i = c1i + c3i;
        float t3r = c1r - c3r, t3i = c1i - c3i;
        float u0r = t0r + t2r, u0i = t0i + t2i;
        float u2r = t0r - t2r, u2i = t0i - t2i;
        float u1r, u1i, u3r, u3i;
        if (!inv) { u1r = t1r + t3i; u1i = t1i - t3r; u3r = t1r - t3i; u3i = t1i + t3r; }
        else      { u1r = t1r - t3i; u1i = t1i + t3r; u3r = t1r + t3i; u3i = t1i - t3r; }
        int o = k + 4 * m * j;
        dr[FPAD(o)]         = u0r;                    di[FPAD(o)]         = u0i;
        dr[FPAD(o + m)]     = w1r * u1r - w1i * u1i;  di[FPAD(o + m)]     = w1r * u1i + w1i * u1r;
        dr[FPAD(o + 2 * m)] = w2r * u2r - w2i * u2i;  di[FPAD(o + 2 * m)] = w2r * u2i + w2i * u2r;
        dr[FPAD(o + 3 * m)] = w3r * u3r - w3i * u3i;  di[FPAD(o + 3 * m)] = w3r * u3i + w3i * u3r;
        __syncthreads();
        float* t;
        t = sr; sr = dr; dr = t;
        t = si; si = di; di = t;
    }
}

// two-array-set version: same sync points, double work per barrier
__device__ __forceinline__ void fft1024_stages_x2(
    float* ar0, float* ai0, float* ar1, float* ai1,
    float* br0, float* bi0, float* br1, float* bi1,
    const float* twr, const float* twi, int tid)
{
    float *sar = ar0, *sai = ai0, *dar = ar1, *dai = ai1;
    float *sbr = br0, *sbi = bi0, *dbr = br1, *dbi = bi1;
    const int Ls[5] = {256, 64, 16, 4, 1};
    const int Ms[5] = {1, 4, 16, 64, 256};
    #pragma unroll
    for (int st = 0; st < 5; st++) {
        const int l = Ls[st], m = Ms[st];
        int j = tid / m, k = tid - j * m;
        int ti = j * (256 / l);
        float w1r = twr[ti], w1i = twi[ti];
        float w2r = w1r * w1r - w1i * w1i, w2i = 2.f * w1r * w1i;
        float w3r = w2r * w1r - w2i * w1i, w3i = w2r * w1i + w2i * w1r;
        int i0 = k + m * j;
        int o = k + 4 * m * j;
        #pragma unroll
        for (int set = 0; set < 2; set++) {
            float *sr = set ? sbr : sar, *si = set ? sbi : sai;
            float *dr = set ? dbr : dar, *di = set ? dbi : dai;
            float c0r = sr[FPAD(i0)],             c0i = si[FPAD(i0)];
            float c1r = sr[FPAD(i0 + m * l)],     c1i = si[FPAD(i0 + m * l)];
            float c2r = sr[FPAD(i0 + 2 * m * l)], c2i = si[FPAD(i0 + 2 * m * l)];
            float c3r = sr[FPAD(i0 + 3 * m * l)], c3i = si[FPAD(i0 + 3 * m * l)];
            float t0r = c0r + c2r, t0i = c0i + c2i;
            float t1r = c0r - c2r, t1i = c0i - c2i;
            float t2r = c1r + c3r, t2i = c1i + c3i;
            float t3r = c1r - c3r, t3i = c1i - c3i;
            float u0r = t0r + t2r, u0i = t0i + t2i;
            float u2r = t0r - t2r, u2i = t0i - t2i;
            float u1r = t1r + t3i, u1i = t1i - t3r;
            float u3r = t1r - t3i, u3i = t1i + t3r;
            dr[FPAD(o)]         = u0r;                    di[FPAD(o)]         = u0i;
            dr[FPAD(o + m)]     = w1r * u1r - w1i * u1i;  di[FPAD(o + m)]     = w1r * u1i + w1i * u1r;
            dr[FPAD(o + 2 * m)] = w2r * u2r - w2i * u2i;  di[FPAD(o + 2 * m)] = w2r * u2i + w2i * u2r;
            dr[FPAD(o + 3 * m)] = w3r * u3r - w3i * u3i;  di[FPAD(o + 3 * m)] = w3r * u3i + w3i * u3r;
        }
        __syncthreads();
        float* t;
        t = sar; sar = dar; dar = t;  t = sai; sai = dai; dai = t;
        t = sbr; sbr = dbr; dbr = t;  t = sbi; sbi = dbi; dbi = t;
    }
}

#define TOKC 16

// bind spectrum accumulate, 2 tokens per iteration
__global__ __launch_bounds__(256) void bind_fft(
    const __half* __restrict__ Kh, const __half* __restrict__ Vh, float* __restrict__ Sacc)
{
    __shared__ float Ar0[1056], Ai0[1056], Ar1[1056], Ai1[1056];
    __shared__ float Br0[1056], Bi0[1056], Br1[1056], Bi1[1056];
    __shared__ float twr[256], twi[256];
    const int tid = threadIdx.x;
    const int b = blockIdx.y;
    const long long base = ((long long)b * Sq + (long long)blockIdx.x * TOKC) * Dd;

    {
        float sv, cv;
        __sincosf(-6.28318530717958647692f * (float)tid / 1024.f, &sv, &cv);
        twr[tid] = cv; twi[tid] = sv;
    }
    float aR0 = 0.f, aI0 = 0.f, aR1 = 0.f, aI1 = 0.f, aR2 = 0.f;

    for (int tok = 0; tok < TOKC; tok += 2) {
        const __half* kr0 = Kh + base + (long long)tok * Dd;
        const __half* vr0 = Vh + base + (long long)tok * Dd;
        const __half* kr1 = kr0 + Dd;
        const __half* vr1 = vr0 + Dd;
        __syncthreads();
        #pragma unroll
        for (int q = 0; q < 4; q++) {
            int i = tid + 256 * q;
            Ar0[FPAD(i)] = __half2float(kr0[i]);
            Ai0[FPAD(i)] = __half2float(vr0[i]);
            Br0[FPAD(i)] = __half2float(kr1[i]);
            Bi0[FPAD(i)] = __half2float(vr1[i]);
        }
        __syncthreads();
        fft1024_stages_x2(Ar0, Ai0, Ar1, Ai1, Br0, Bi0, Br1, Bi1, twr, twi, tid);
        // results in Ar1/Ai1 and Br1/Bi1 (odd number of swaps: 5 stages -> lands in *1)

        #pragma unroll
        for (int set = 0; set < 2; set++) {
            const float* Rr = set ? Br1 : Ar1;
            const float* Ri = set ? Bi1 : Ai1;
            #pragma unroll
            for (int h = 0; h < 2; h++) {
                int f = tid + h * 256;
                int nf = (1024 - f) & 1023;
                float Zr = Rr[FPAD(f)],  Zi = Ri[FPAD(f)];
                float Brv = Rr[FPAD(nf)], Biv = Ri[FPAD(nf)];
                float Kr_ = 0.5f * (Zr + Brv), Ki_ = 0.5f * (Zi - Biv);
                float Vr_ = 0.5f * (Zi + Biv), Vi_ = 0.5f * (Brv - Zr);
                float Pr = Kr_ * Vr_ - Ki_ * Vi_;
                float Pi = Kr_ * Vi_ + Ki_ * Vr_;
                if (h == 0) { aR0 += Pr; aI0 += Pi; }
                else        { aR1 += Pr; aI1 += Pi; }
            }
            if (tid == 0) {
                float Zr = Rr[FPAD(512)], Zi = Ri[FPAD(512)];
                aR2 += Zr * Zi;
            }
        }
    }
    float* Sb = Sacc + b * 513 * 2;
    atomicAdd(&Sb[tid * 2 + 0], aR0);
    atomicAdd(&Sb[tid * 2 + 1], aI0);
    atomicAdd(&Sb[(tid + 256) * 2 + 0], aR1);
    atomicAdd(&Sb[(tid + 256) * 2 + 1], aI1);
    if (tid == 0) atomicAdd(&Sb[512 * 2 + 0], aR2);
}

// irfft of the accumulated spectrum -> s_b[1024]
__global__ __launch_bounds__(256) void irfft_s(const float* __restrict__ Sacc,
                                               float* __restrict__ s)
{
    __shared__ float Ar0[1056], Ai0[1056], Ar1[1056], Ai1[1056];
    __shared__ float twr[256], twi[256];
    const int tid = threadIdx.x;
    const int b = blockIdx.x;
    const float* Sb = Sacc + b * 513 * 2;
    {
        float sv, cv;
        __sincosf(6.28318530717958647692f * (float)tid / 1024.f, &sv, &cv);
        twr[tid] = cv; twi[tid] = sv;
    }
    #pragma unroll
    for (int q = 0; q < 4; q++) {
        int i = tid + 256 * q;
        float re, im;
        if (i <= 512) { re = Sb[i * 2]; im = Sb[i * 2 + 1]; }
        else          { re = Sb[(1024 - i) * 2]; im = -Sb[(1024 - i) * 2 + 1]; }
        Ar0[FPAD(i)] = re;
        Ai0[FPAD(i)] = im;
    }
    __syncthreads();
    fft1024_stages(Ar0, Ai0, Ar1, Ai1, twr, twi, tid, 1);
    #pragma unroll
    for (int q = 0; q < 4; q++) {
        int i = tid + 256 * q;
        s[b * Dd + i] = Ar1[FPAD(i)] * (1.f / 1024.f);
    }
}

// W2[d][n] = iDFT( Shat_b * conj(What_d) ); one CTA per Wq row
__global__ __launch_bounds__(256) void fft_w2(
    const float* __restrict__ Wq, const float* __restrict__ Sacc,
    __half* __restrict__ W2tmp)
{
    __shared__ float Ar0[1056], Ai0[1056], Ar1[1056], Ai1[1056];
    __shared__ float twf_r[256], twf_i[256], twb_r[256], twb_i[256];
    const int tid = threadIdx.x;
    const int d = blockIdx.x;
    {
        float sv, cv;
        __sincosf(-6.28318530717958647692f * (float)tid / 1024.f, &sv, &cv);
        twf_r[tid] = cv; twf_i[tid] = sv;
        twb_r[tid] = cv; twb_i[tid] = -sv;
    }
    const float* wrow = Wq + (long long)d * Dd;
    #pragma unroll
    for (int q = 0; q < 4; q++) {
        int i = tid + 256 * q;
        Ar0[FPAD(i)] = wrow[i];
        Ai0[FPAD(i)] = 0.f;
    }
    __syncthreads();
    fft1024_stages(Ar0, Ai0, Ar1, Ai1, twf_r, twf_i, tid, 0);

    float Wr[4], Wi[4];
    #pragma unroll
    for (int q = 0; q < 4; q++) {
        int f = tid + 256 * q;
        Wr[q] = Ar1[FPAD(f)];
        Wi[q] = Ai1[FPAD(f)];
    }

    for (int b = 0; b < Bsz; b++) {
        const float* Sb = Sacc + b * 513 * 2;
        #pragma unroll
        for (int q = 0; q < 4; q++) {
            int f = tid + 256 * q;
            float Sr, Si;
            if (f <= 512) { Sr = Sb[f * 2]; Si = Sb[f * 2 + 1]; }
            else          { Sr = Sb[(1024 - f) * 2]; Si = -Sb[(1024 - f) * 2 + 1]; }
            Ar0[FPAD(f)] = Sr * Wr[q] + Si * Wi[q];
            Ai0[FPAD(f)] = Si * Wr[q] - Sr * Wi[q];
        }
        __syncthreads();
        fft1024_stages(Ar0, Ai0, Ar1, Ai1, twb_r, twb_i, tid, 1);
        __half* dst = W2tmp + ((long long)b << 20) + ((long long)d << 10);
        #pragma unroll
        for (int q = 0; q < 4; q++) {
            int i = tid + 256 * q;
            dst[i] = __float2half(Ar1[FPAD(i)] * (1.f / 1024.f));
        }
    }
}

// ---------------- prep kernels ----------------
__global__ void zero_S(float* p, int n)
{
    int i = blockIdx.x * 256 + threadIdx.x;
    if (i < n) p[i] = 0.f;
}

__global__ void conv_f16v(const float4* __restrict__ x, __half2* __restrict__ h, long long n4)
{
    long long i = (long long)blockIdx.x * blockDim.x + threadIdx.x;
    if (i < n4) {
        float4 v = x[i];
        h[i * 2 + 0] = __half2{__float2half(v.x), __float2half(v.y)};
        h[i * 2 + 1] = __half2{__float2half(v.z), __float2half(v.w)};
    }
}

__global__ void transpose_conv_f16(const float* __restrict__ src, __half* __restrict__ dst,
                                   int R, int C)
{
    __shared__ float t[32][33];
    int c0 = blockIdx.x * 32, r0 = blockIdx.y * 32;
    int tx = threadIdx.x, ty = threadIdx.y;
    #pragma unroll
    for (int k = 0; k < 32; k += 8)
        t[ty + k][tx] = src[(long long)(r0 + ty + k) * C + c0 + tx];
    __syncthreads();
    #pragma unroll
    for (int k = 0; k < 32; k += 8)
        dst[(long long)(c0 + ty + k) * R + r0 + tx] = __float2half(t[tx][ty + k]);
}

__global__ void transpose_f16(const __half* __restrict__ s, __half* __restrict__ d,
                              int R, int C, long long sIn, long long sOut)
{
    __shared__ __half t[64][65];
    int b = blockIdx.z;
    s += (long long)b * sIn; d += (long long)b * sOut;
    int c0 = blockIdx.x * 64, r0 = blockIdx.y * 64;
    int tid = threadIdx.x;
    #pragma unroll
    for (int it = 0; it < 8; it++) {
        int id = tid + it * 256;
        int row = id >> 5, cp = (id & 31) * 2;
        __half2 v = *reinterpret_cast<const __half2*>(s + (long long)(r0 + row) * C + c0 + cp);
        t[row][cp] = v.x; t[row][cp + 1] = v.y;
    }
    __syncthreads();
    #pragma unroll
    for (int it = 0; it < 8; it++) {
        int id = tid + it * 256;
        int cc = id >> 5, rp = (id & 31) * 2;
        __half2 v = { t[rp][cc], t[rp + 1][cc] };
        *reinterpret_cast<__half2*>(d + (long long)(c0 + cc) * R + r0 + rp) = v;
    }
}

__global__ void compute_r(const float* __restrict__ s, const float* __restrict__ bq,
                          float* __restrict__ r)
{
    int b = blockIdx.y;
    int n = blockIdx.x * 256 + threadIdx.x;
    float acc = 0.f;
    for (int m = 0; m < Dd; m++)
        acc += bq[m] * s[b * Dd + ((m + n) & (Dd - 1))];
    r[b * Dd + n] = acc;
}

// ---------------- launcher ----------------
extern "C" void kernel_launch(void* const* d_in, const int* in_sizes, int n_in,
                              void* d_out, int out_size)
{
    const float* x  = (const float*)d_in[0];
    const float* Wq = (const float*)d_in[1];
    const float* bq = (const float*)d_in[2];
    const float* Wk = (const float*)d_in[3];
    const float* bk = (const float*)d_in[4];
    const float* Wv = (const float*)d_in[5];
    const float* bv = (const float*)d_in[6];
    float* out = (float*)d_out;

    __half *xh, *WkTs, *WvTs, *Kh, *Vh, *W2tmp, *W2Ts;
    float *S, *s, *r;
    cudaGetSymbolAddress((void**)&xh, g_xh);
    cudaGetSymbolAddress((void**)&WkTs, g_WkTs); cudaGetSymbolAddress((void**)&WvTs, g_WvTs);
    cudaGetSymbolAddress((void**)&Kh, g_Kh);     cudaGetSymbolAddress((void**)&Vh, g_Vh);
    cudaGetSymbolAddress((void**)&S, g_S);
    cudaGetSymbolAddress((void**)&s, g_s);       cudaGetSymbolAddress((void**)&r, g_r);
    cudaGetSymbolAddress((void**)&W2tmp, g_W2tmp);
    cudaGetSymbolAddress((void**)&W2Ts, g_W2Ts);

    cudaFuncSetAttribute(gemm_hmma, cudaFuncAttributeMaxDynamicSharedMemorySize, DSMEM1);

    const long long nBS = (long long)BS * Dd;       // 16M
    const long long dd  = (long long)Dd * Dd;       // 1M
    const long long sd  = (long long)Sq * Dd;       // 4M

    // 0) input conversion
    conv_f16v<<<(unsigned)(nBS / 4 / 256), 256>>>((const float4*)x, (__half2*)xh, nBS / 4);
    transpose_conv_f16<<<dim3(Dd / 32, Dd / 32), dim3(32, 8)>>>(Wk, WkTs, Dd, Dd);
    transpose_conv_f16<<<dim3(Dd / 32, Dd / 32), dim3(32, 8)>>>(Wv, WvTs, Dd, Dd);

    // 1) K = x@Wk + bk ; V = x@Wv + bv  -> fp16
    gemm_hmma<<<dim3(Dd / 128, BS / 128, 1), 128, DSMEM1>>>(
        xh, WkTs, bk, nullptr, Kh, Dd, Dd, 0, 0, 0, 0);
    gemm_hmma<<<dim3(Dd / 128, BS / 128, 1), 128, DSMEM1>>>(
        xh, WvTs, bv, nullptr, Vh, Dd, Dd, 0, 0, 0, 0);

    // 2) Shat_b = sum_t rfft(k_t)*rfft(v_t);  s_b = irfft(Shat_b)
    zero_S<<<(Bsz * 513 * 2 + 255) / 256, 256>>>(S, Bsz * 513 * 2);
    bind_fft<<<dim3(Sq / TOKC, Bsz), 256>>>(Kh, Vh, S);
    irfft_s<<<Bsz, 256>>>(S, s);

    // 3) r_b = bq @ M_b
    compute_r<<<dim3(Dd / 256, Bsz), 256>>>(s, bq, r);

    // 4) W2 rows via spectral unbind; transpose to [n][d]
    fft_w2<<<Dd, 256>>>(Wq, S, W2tmp);
    transpose_f16<<<dim3(Dd / 64, Dd / 64, Bsz), 256>>>(W2tmp, W2Ts, Dd, Dd, dd, dd);

    // 5) out_b = x_b @ W2_b + r_b  (fp32 out)
    gemm_hmma<<<dim3(Dd / 128, Sq / 128, Bsz), 128, DSMEM1>>>(
        xh, W2Ts, r, out, nullptr, Dd, Dd, sd, dd, Dd, sd);
}

// round 12
// speedup vs baseline: 1.0331x; 1.0331x over previous
#include <cuda_runtime.h>
#include <cuda_fp16.h>
#include <stdint.h>

#define Bsz 4
#define Sq  4096
#define Dd  1024
#define BS  (Bsz * Sq)   // 16384

// ---------------- scratch (device globals — allocation is forbidden) ----------------
__device__ __align__(256) __half g_xh[(long long)BS * Dd];
__device__ __align__(256) __half g_WkTs[Dd * Dd];
__device__ __align__(256) __half g_WvTs[Dd * Dd];
__device__ __align__(256) __half g_Kh[(long long)BS * Dd];
__device__ __align__(256) __half g_Vh[(long long)BS * Dd];
__device__ __align__(256) float  g_S[Bsz * 513 * 2];
__device__ __align__(256) float  g_s[Bsz * Dd];
__device__ __align__(256) float  g_r[Bsz * Dd];
__device__ __align__(256) __half g_W2tmp[(long long)Bsz * Dd * Dd];  // [b][d][n]
__device__ __align__(256) __half g_W2Ts[(long long)Bsz * Dd * Dd];   // [b][n][d]

// ---------------- PTX helpers ----------------
__device__ __forceinline__ uint32_t smem_u32(const void* p) {
    uint32_t a;
    asm("{ .reg .u64 t; cvta.to.shared.u64 t, %1; cvt.u32.u64 %0, t; }" : "=r"(a) : "l"(p));
    return a;
}
__device__ __forceinline__ void cp16(uint32_t dst, const void* src) {
    asm volatile("cp.async.cg.shared.global [%0], [%1], 16;" :: "r"(dst), "l"(src));
}
__device__ __forceinline__ void cp_commit() { asm volatile("cp.async.commit_group;" ::: "memory"); }
template<int N> __device__ __forceinline__ void cp_wait() {
    asm volatile("cp.async.wait_group %0;" :: "n"(N) : "memory");
}

__device__ __forceinline__ void ldsm_x4(uint32_t& r0, uint32_t& r1, uint32_t& r2, uint32_t& r3,
                                        uint32_t addr) {
    asm volatile("ldmatrix.sync.aligned.m8n8.x4.shared.b16 {%0,%1,%2,%3}, [%4];"
                 : "=r"(r0), "=r"(r1), "=r"(r2), "=r"(r3) : "r"(addr));
}
__device__ __forceinline__ void mma_fp16(float& c0, float& c1, float& c2, float& c3,
                                         uint32_t a0, uint32_t a1, uint32_t a2, uint32_t a3,
                                         uint32_t b0, uint32_t b1) {
    asm volatile(
        "mma.sync.aligned.m16n8k16.row.col.f32.f16.f16.f32 "
        "{%0,%1,%2,%3}, {%4,%5,%6,%7}, {%8,%9}, {%0,%1,%2,%3};"
        : "+f"(c0), "+f"(c1), "+f"(c2), "+f"(c3)
        : "r"(a0), "r"(a1), "r"(a2), "r"(a3), "r"(b0), "r"(b1));
}

// ---------------- fp16 HMMA GEMM: C[M,N] = Ah @ Bs^T (+bias[n]) ----------------
// CTA tile 128x128x64, 128 threads = 4 warps (2x2), warp tile 64x64, 2 CTAs/SM.
// 3-stage cp.async ring, ONE __syncthreads per chunk, fragment double-buffering.
#define STG1 32768
#define DSMEM1 (3 * STG1)     // 98304

__global__ __launch_bounds__(128, 2) void gemm_hmma(
    const __half* __restrict__ Ah,
    const __half* __restrict__ Bs,
    const float* __restrict__ bias, float* __restrict__ Cf,
    __half* __restrict__ Ch,
    int N, int Ktot,
    long long sA, long long sB, long long sBias, long long sC)
{
    extern __shared__ __align__(128) char smem[];
    const int tid = threadIdx.x;
    const int wid = tid >> 5, lid = tid & 31;
    const int bz = blockIdx.z;
    const long long bm = (long long)blockIdx.y * 128;
    const long long bn = (long long)blockIdx.x * 128;

    const __half* gA0 = Ah + bz * sA + bm * Ktot;
    const __half* gB = Bs + bz * sB + bn * Ktot;
    const float* biasp = bias ? bias + bz * sBias : nullptr;

    const uint32_t sb = smem_u32(smem);
    const int wm = (wid & 1) * 64;
    const int wn = (wid >> 1) * 64;

    float acc[4][8][4];
    #pragma unroll
    for (int a = 0; a < 4; a++)
        #pragma unroll
        for (int b = 0; b < 8; b++)
            #pragma unroll
            for (int c = 0; c < 4; c++) acc[a][b][c] = 0.f;

    auto load_chunk = [&](int slot, int k0) {
        const uint32_t buf = sb + slot * STG1;
        #pragma unroll
        for (int it = 0; it < 8; it++) {
            int id = tid + it * 128;
            int r = id >> 3, c = id & 7;
            cp16(buf + r * 128 + (((c ^ r) & 7) << 4),
                 gA0 + (long long)r * Ktot + k0 + c * 8);
        }
        #pragma unroll
        for (int it = 0; it < 8; it++) {
            int id = tid + it * 128;
            int r = id >> 3, c = id & 7;
            cp16(buf + 16384 + r * 128 + ((c ^ (r & 7)) << 4),
                 gB + (long long)r * Ktot + k0 + c * 8);
        }
        cp_commit();
    };

    const int nc = Ktot >> 6;        // 16
    load_chunk(0, 0);
    load_chunk(1, 64);

    const int a_row = wm + (lid & 15);
    const int a_hi  = lid >> 4;
    const int b_row = wn + (lid & 7) + ((lid >> 4) & 1) * 8;
    const int b_hi  = (lid >> 3) & 1;

    uint32_t Af[2][4][4], Bf[2][4][4];
    auto ldsm_frags = [&](uint32_t buf, int kk, uint32_t A_[4][4], uint32_t B_[4][4]) {
        #pragma unroll
        for (int mb = 0; mb < 4; mb++) {
            int r = a_row + mb * 16;
            int c = kk * 2 + a_hi;
            ldsm_x4(A_[mb][0], A_[mb][1], A_[mb][2], A_[mb][3],
                    buf + r * 128 + ((c ^ (r & 7)) << 4));
        }
        #pragma unroll
        for (int nq = 0; nq < 4; nq++) {
            int r = b_row + nq * 16;
            int c = kk * 2 + b_hi;
            ldsm_x4(B_[nq][0], B_[nq][1], B_[nq][2], B_[nq][3],
                    buf + 16384 + r * 128 + ((c ^ (r & 7)) << 4));
        }
    };

    int slot = 0;
    for (int i = 0; i < nc; i++) {
        if (i + 1 < nc) cp_wait<1>(); else cp_wait<0>();
        __syncthreads();
        // safe to overwrite slot (i+2)%3 == (i-1)%3: the barrier above ordered
        // iter i-1's MMA reads before these cp.async writes.
        if (i + 2 < nc) {
            int ns = slot + 2; if (ns >= 3) ns -= 3;
            load_chunk(ns, (i + 2) << 6);
        }
        const uint32_t buf = sb + slot * STG1;
        ldsm_frags(buf, 0, Af[0], Bf[0]);
        #pragma unroll
        for (int kk = 0; kk < 4; kk++) {
            const int cur = kk & 1;
            if (kk < 3) ldsm_frags(buf, kk + 1, Af[cur ^ 1], Bf[cur ^ 1]);
            #pragma unroll
            for (int mb = 0; mb < 4; mb++)
                #pragma unroll
                for (int nq = 0; nq < 4; nq++)
                    #pragma unroll
                    for (int half = 0; half < 2; half++) {
                        float* c = acc[mb][nq * 2 + half];
                        mma_fp16(c[0], c[1], c[2], c[3],
                                 Af[cur][mb][0], Af[cur][mb][1], Af[cur][mb][2], Af[cur][mb][3],
                                 Bf[cur][nq][half * 2], Bf[cur][nq][half * 2 + 1]);
                    }
        }
        if (++slot == 3) slot = 0;
    }

    const int er = lid >> 2;
    const int ec = (lid & 3) * 2;
    #pragma unroll
    for (int mb = 0; mb < 4; mb++) {
        #pragma unroll
        for (int nb = 0; nb < 8; nb++) {
            const float* c = acc[mb][nb];
            long long col = bn + wn + nb * 8 + ec;
            float bx = 0.f, by = 0.f;
            if (biasp) { bx = biasp[col]; by = biasp[col + 1]; }
            long long r0 = bm + wm + mb * 16 + er;
            float v0 = c[0] + bx, v1 = c[1] + by;
            float v2 = c[2] + bx, v3 = c[3] + by;
            if (Cf) {
                float* Cb = Cf + bz * sC;
                *reinterpret_cast<float2*>(Cb + r0 * N + col) = make_float2(v0, v1);
                *reinterpret_cast<float2*>(Cb + (r0 + 8) * N + col) = make_float2(v2, v3);
            } else {
                __half2 s0 = { __float2half(v0), __float2half(v1) };
                __half2 s1 = { __float2half(v2), __float2half(v3) };
                __half* Hb = Ch + bz * sC;
                *reinterpret_cast<__half2*>(Hb + r0 * N + col) = s0;
                *reinterpret_cast<__half2*>(Hb + (r0 + 8) * N + col) = s1;
            }
        }
    }
}

// ---------------- FFT machinery (radix-4 Stockham, N=1024, 256 threads) ----------------
#define FPAD(i) ((i) + ((i) >> 5))

__device__ __forceinline__ void fft1024_stages(
    float* br0, float* bi0, float* br1, float* bi1,
    const float* twr, const float* twi, int tid, int inv)
{
    float *sr = br0, *si = bi0, *dr = br1, *di = bi1;
    const int Ls[5] = {256, 64, 16, 4, 1};
    const int Ms[5] = {1, 4, 16, 64, 256};
    #pragma unroll
    for (int st = 0; st < 5; st++) {
        const int l = Ls[st], m = Ms[st];
        int j = tid / m, k = tid - j * m;
        int ti = j * (256 / l);
        float w1r = twr[ti], w1i = twi[ti];
        float w2r = w1r * w1r - w1i * w1i, w2i = 2.f * w1r * w1i;
        float w3r = w2r * w1r - w2i * w1i, w3i = w2r * w1i + w2i * w1r;
        int i0 = k + m * j;
        float c0r = sr[FPAD(i0)],             c0i = si[FPAD(i0)];
        float c1r = sr[FPAD(i0 + m * l)],     c1i = si[FPAD(i0 + m * l)];
        float c2r = sr[FPAD(i0 + 2 * m * l)], c2i = si[FPAD(i0 + 2 * m * l)];
        float c3r = sr[FPAD(i0 + 3 * m * l)], c3i = si[FPAD(i0 + 3 * m * l)];
        float t0r = c0r + c2r, t0i = c0i + c2i;
        float t1r = c0r - c2r, t1i = c0i - c2i;
        float t2r = c1r + c3r, t2i = c1i + c3i;
        float t3r = c1r - c3r, t3i = c1i - c3i;
        float u0r = t0r + t2r, u0i = t0i + t2i;
        float u2r = t0r - t2r, u2i = t0i - t2i;
        float u1r, u1i, u3r, u3i;
        if (!inv) { u1r = t1r + t3i; u1i = t1i - t3r; u3r = t1r - t3i; u3i = t1i + t3r; }
        else      { u1r = t1r - t3i; u1i = t1i + t3r; u3r = t1r + t3i; u3i = t1i - t3r; }
        int o = k + 4 * m * j;
        dr[FPAD(o)]         = u0r;                    di[FPAD(o)]         = u0i;
        dr[FPAD(o + m)]     = w1r * u1r - w1i * u1i;  di[FPAD(o + m)]     = w1r * u1i + w1i * u1r;
        dr[FPAD(o + 2 * m)] = w2r * u2r - w2i * u2i;  di[FPAD(o + 2 * m)] = w2r * u2i + w2i * u2r;
        dr[FPAD(o + 3 * m)] = w3r * u3r - w3i * u3i;  di[FPAD(o + 3 * m)] = w3r * u3i + w3i * u3r;
        __syncthreads();
        float* t;
        t = sr; sr = dr; dr = t;
        t = si; si = di; di = t;
    }
}

__device__ __forceinline__ void fft1024_stages_x2(
    float* ar0, float* ai0, float* ar1, float* ai1,
    float* br0, float* bi0, float* br1, float* bi1,
    const float* twr, const float* twi, int tid)
{
    float *sar = ar0, *sai = ai0, *dar = ar1, *dai = ai1;
    float *sbr = br0, *sbi = bi0, *dbr = br1, *dbi = bi1;
    const int Ls[5] = {256, 64, 16, 4, 1};
    const int Ms[5] = {1, 4, 16, 64, 256};
    #pragma unroll
    for (int st = 0; st < 5; st++) {
        const int l = Ls[st], m = Ms[st];
        int j = tid / m, k = tid - j * m;
        int ti = j * (256 / l);
        float w1r = twr[ti], w1i = twi[ti];
        float w2r = w1r * w1r - w1i * w1i, w2i = 2.f * w1r * w1i;
        float w3r = w2r * w1r - w2i * w1i, w3i = w2r * w1i + w2i * w1r;
        int i0 = k + m * j;
        int o = k + 4 * m * j;
        #pragma unroll
        for (int set = 0; set < 2; set++) {
            float *sr = set ? sbr : sar, *si = set ? sbi : sai;
            float *dr = set ? dbr : dar, *di = set ? dbi : dai;
            float c0r = sr[FPAD(i0)],             c0i = si[FPAD(i0)];
            float c1r = sr[FPAD(i0 + m * l)],     c1i = si[FPAD(i0 + m * l)];
            float c2r = sr[FPAD(i0 + 2 * m * l)], c2i = si[FPAD(i0 + 2 * m * l)];
            float c3r = sr[FPAD(i0 + 3 * m * l)], c3i = si[FPAD(i0 + 3 * m * l)];
            float t0r = c0r + c2r, t0i = c0i + c2i;
            float t1r = c0r - c2r, t1i = c0i - c2i;
            float t2r = c1r + c3r, t2i = c1i + c3i;
            float t3r = c1r - c3r, t3i = c1i - c3i;
            float u0r = t0r + t2r, u0i = t0i + t2i;
            float u2r = t0r - t2r, u2i = t0i - t2i;
            float u1r = t1r + t3i, u1i = t1i - t3r;
            float u3r = t1r - t3i, u3i = t1i + t3r;
            dr[FPAD(o)]         = u0r;                    di[FPAD(o)]         = u0i;
            dr[FPAD(o + m)]     = w1r * u1r - w1i * u1i;  di[FPAD(o + m)]     = w1r * u1i + w1i * u1r;
            dr[FPAD(o + 2 * m)] = w2r * u2r - w2i * u2i;  di[FPAD(o + 2 * m)] = w2r * u2i + w2i * u2r;
            dr[FPAD(o + 3 * m)] = w3r * u3r - w3i * u3i;  di[FPAD(o + 3 * m)] = w3r * u3i + w3i * u3r;
        }
        __syncthreads();
        float* t;
        t = sar; sar = dar; dar = t;  t = sai; sai = dai; dai = t;
        t = sbr; sbr = dbr; dbr = t;  t = sbi; sbi = dbi; dbi = t;
    }
}

#define TOKC 16

__global__ __launch_bounds__(256) void bind_fft(
    const __half* __restrict__ Kh, const __half* __restrict__ Vh, float* __restrict__ Sacc)
{
    __shared__ float Ar0[1056], Ai0[1056], Ar1[1056], Ai1[1056];
    __shared__ float Br0[1056], Bi0[1056], Br1[1056], Bi1[1056];
    __shared__ float twr[256], twi[256];
    const int tid = threadIdx.x;
    const int b = blockIdx.y;
    const long long base = ((long long)b * Sq + (long long)blockIdx.x * TOKC) * Dd;

    {
        float sv, cv;
        __sincosf(-6.28318530717958647692f * (float)tid / 1024.f, &sv, &cv);
        twr[tid] = cv; twi[tid] = sv;
    }
    float aR0 = 0.f, aI0 = 0.f, aR1 = 0.f, aI1 = 0.f, aR2 = 0.f;

    for (int tok = 0; tok < TOKC; tok += 2) {
        const __half* kr0 = Kh + base + (long long)tok * Dd;
        const __half* vr0 = Vh + base + (long long)tok * Dd;
        const __half* kr1 = kr0 + Dd;
        const __half* vr1 = vr0 + Dd;
        __syncthreads();
        #pragma unroll
        for (int q = 0; q < 4; q++) {
            int i = tid + 256 * q;
            Ar0[FPAD(i)] = __half2float(kr0[i]);
            Ai0[FPAD(i)] = __half2float(vr0[i]);
            Br0[FPAD(i)] = __half2float(kr1[i]);
            Bi0[FPAD(i)] = __half2float(vr1[i]);
        }
        __syncthreads();
        fft1024_stages_x2(Ar0, Ai0, Ar1, Ai1, Br0, Bi0, Br1, Bi1, twr, twi, tid);

        #pragma unroll
        for (int set = 0; set < 2; set++) {
            const float* Rr = set ? Br1 : Ar1;
            const float* Ri = set ? Bi1 : Ai1;
            #pragma unroll
            for (int h = 0; h < 2; h++) {
                int f = tid + h * 256;
                int nf = (1024 - f) & 1023;
                float Zr = Rr[FPAD(f)],  Zi = Ri[FPAD(f)];
                float Brv = Rr[FPAD(nf)], Biv = Ri[FPAD(nf)];
                float Kr_ = 0.5f * (Zr + Brv), Ki_ = 0.5f * (Zi - Biv);
                float Vr_ = 0.5f * (Zi + Biv), Vi_ = 0.5f * (Brv - Zr);
                float Pr = Kr_ * Vr_ - Ki_ * Vi_;
                float Pi = Kr_ * Vi_ + Ki_ * Vr_;
                if (h == 0) { aR0 += Pr; aI0 += Pi; }
                else        { aR1 += Pr; aI1 += Pi; }
            }
            if (tid == 0) {
                float Zr = Rr[FPAD(512)], Zi = Ri[FPAD(512)];
                aR2 += Zr * Zi;
            }
        }
    }
    float* Sb = Sacc + b * 513 * 2;
    atomicAdd(&Sb[tid * 2 + 0], aR0);
    atomicAdd(&Sb[tid * 2 + 1], aI0);
    atomicAdd(&Sb[(tid + 256) * 2 + 0], aR1);
    atomicAdd(&Sb[(tid + 256) * 2 + 1], aI1);
    if (tid == 0) atomicAdd(&Sb[512 * 2 + 0], aR2);
}

__global__ __launch_bounds__(256) void irfft_s(const float* __restrict__ Sacc,
                                               float* __restrict__ s)
{
    __shared__ float Ar0[1056], Ai0[1056], Ar1[1056], Ai1[1056];
    __shared__ float twr[256], twi[256];
    const int tid = threadIdx.x;
    const int b = blockIdx.x;
    const float* Sb = Sacc + b * 513 * 2;
    {
        float sv, cv;
        __sincosf(6.28318530717958647692f * (float)tid / 1024.f, &sv, &cv);
        twr[tid] = cv; twi[tid] = sv;
    }
    #pragma unroll
    for (int q = 0; q < 4; q++) {
        int i = tid + 256 * q;
        float re, im;
        if (i <= 512) { re = Sb[i * 2]; im = Sb[i * 2 + 1]; }
        else          { re = Sb[(1024 - i) * 2]; im = -Sb[(1024 - i) * 2 + 1]; }
        Ar0[FPAD(i)] = re;
        Ai0[FPAD(i)] = im;
    }
    __syncthreads();
    fft1024_stages(Ar0, Ai0, Ar1, Ai1, twr, twi, tid, 1);
    #pragma unroll
    for (int q = 0; q < 4; q++) {
        int i = tid + 256 * q;
        s[b * Dd + i] = Ar1[FPAD(i)] * (1.f / 1024.f);
    }
}

__global__ __launch_bounds__(256) void fft_w2(
    const float* __restrict__ Wq, const float* __restrict__ Sacc,
    __half* __restrict__ W2tmp)
{
    __shared__ float Ar0[1056], Ai0[1056], Ar1[1056], Ai1[1056];
    __shared__ float twf_r[256], twf_i[256], twb_r[256], twb_i[256];
    const int tid = threadIdx.x;
    const int d = blockIdx.x;
    {
        float sv, cv;
        __sincosf(-6.28318530717958647692f * (float)tid / 1024.f, &sv, &cv);
        twf_r[tid] = cv; twf_i[tid] = sv;
        twb_r[tid] = cv; twb_i[tid] = -sv;
    }
    const float* wrow = Wq + (long long)d * Dd;
    #pragma unroll
    for (int q = 0; q < 4; q++) {
        int i = tid + 256 * q;
        Ar0[FPAD(i)] = wrow[i];
        Ai0[FPAD(i)] = 0.f;
    }
    __syncthreads();
    fft1024_stages(Ar0, Ai0, Ar1, Ai1, twf_r, twf_i, tid, 0);

    float Wr[4], Wi[4];
    #pragma unroll
    for (int q = 0; q < 4; q++) {
        int f = tid + 256 * q;
        Wr[q] = Ar1[FPAD(f)];
        Wi[q] = Ai1[FPAD(f)];
    }

    for (int b = 0; b < Bsz; b++) {
        const float* Sb = Sacc + b * 513 * 2;
        #pragma unroll
        for (int q = 0; q < 4; q++) {
            int f = tid + 256 * q;
            float Sr, Si;
            if (f <= 512) { Sr = Sb[f * 2]; Si = Sb[f * 2 + 1]; }
            else          { Sr = Sb[(1024 - f) * 2]; Si = -Sb[(1024 - f) * 2 + 1]; }
            Ar0[FPAD(f)] = Sr * Wr[q] + Si * Wi[q];
            Ai0[FPAD(f)] = Si * Wr[q] - Sr * Wi[q];
        }
        __syncthreads();
        fft1024_stages(Ar0, Ai0, Ar1, Ai1, twb_r, twb_i, tid, 1);
        __half* dst = W2tmp + ((long long)b << 20) + ((long long)d << 10);
        #pragma unroll
        for (int q = 0; q < 4; q++) {
            int i = tid + 256 * q;
            dst[i] = __float2half(Ar1[FPAD(i)] * (1.f / 1024.f));
        }
    }
}

// ---------------- prep kernels ----------------
__global__ void zero_S(float* p, int n)
{
    int i = blockIdx.x * 256 + threadIdx.x;
    if (i < n) p[i] = 0.f;
}

__global__ void conv_f16v(const float4* __restrict__ x, __half2* __restrict__ h, long long n4)
{
    long long i = (long long)blockIdx.x * blockDim.x + threadIdx.x;
    if (i < n4) {
        float4 v = x[i];
        h[i * 2 + 0] = __half2{__float2half(v.x), __float2half(v.y)};
        h[i * 2 + 1] = __half2{__float2half(v.z), __float2half(v.w)};
    }
}

__global__ void transpose_conv_f16(const float* __restrict__ src, __half* __restrict__ dst,
                                   int R, int C)
{
    __shared__ float t[32][33];
    int c0 = blockIdx.x * 32, r0 = blockIdx.y * 32;
    int tx = threadIdx.x, ty = threadIdx.y;
    #pragma unroll
    for (int k = 0; k < 32; k += 8)
        t[ty + k][tx] = src[(long long)(r0 + ty + k) * C + c0 + tx];
    __syncthreads();
    #pragma unroll
    for (int k = 0; k < 32; k += 8)
        dst[(long long)(c0 + ty + k) * R + r0 + tx] = __float2half(t[tx][ty + k]);
}

__global__ void transpose_f16(const __half* __restrict__ s, __half* __restrict__ d,
                              int R, int C, long long sIn, long long sOut)
{
    __shared__ __half t[64][65];
    int b = blockIdx.z;
    s += (long long)b * sIn; d += (long long)b * sOut;
    int c0 = blockIdx.x * 64, r0 = blockIdx.y * 64;
    int tid = threadIdx.x;
    #pragma unroll
    for (int it = 0; it < 8; it++) {
        int id = tid + it * 256;
        int row = id >> 5, cp = (id & 31) * 2;
        __half2 v = *reinterpret_cast<const __half2*>(s + (long long)(r0 + row) * C + c0 + cp);
        t[row][cp] = v.x; t[row][cp + 1] = v.y;
    }
    __syncthreads();
    #pragma unroll
    for (int it = 0; it < 8; it++) {
        int id = tid + it * 256;
        int cc = id >> 5, rp = (id & 31) * 2;
        __half2 v = { t[rp][cc], t[rp + 1][cc] };
        *reinterpret_cast<__half2*>(d + (long long)(c0 + cc) * R + r0 + rp) = v;
    }
}

__global__ void compute_r(const float* __restrict__ s, const float* __restrict__ bq,
                          float* __restrict__ r)
{
    int b = blockIdx.y;
    int n = blockIdx.x * 256 + threadIdx.x;
    float acc = 0.f;
    for (int m = 0; m < Dd; m++)
        acc += bq[m] * s[b * Dd + ((m + n) & (Dd - 1))];
    r[b * Dd + n] = acc;
}

// ---------------- launcher ----------------
extern "C" void kernel_launch(void* const* d_in, const int* in_sizes, int n_in,
                              void* d_out, int out_size)
{
    const float* x  = (const float*)d_in[0];
    const float* Wq = (const float*)d_in[1];
    const float* bq = (const float*)d_in[2];
    const float* Wk = (const float*)d_in[3];
    const float* bk = (const float*)d_in[4];
    const float* Wv = (const float*)d_in[5];
    const float* bv = (const float*)d_in[6];
    float* out = (float*)d_out;

    __half *xh, *WkTs, *WvTs, *Kh, *Vh, *W2tmp, *W2Ts;
    float *S, *s, *r;
    cudaGetSymbolAddress((void**)&xh, g_xh);
    cudaGetSymbolAddress((void**)&WkTs, g_WkTs); cudaGetSymbolAddress((void**)&WvTs, g_WvTs);
    cudaGetSymbolAddress((void**)&Kh, g_Kh);     cudaGetSymbolAddress((void**)&Vh, g_Vh);
    cudaGetSymbolAddress((void**)&S, g_S);
    cudaGetSymbolAddress((void**)&s, g_s);       cudaGetSymbolAddress((void**)&r, g_r);
    cudaGetSymbolAddress((void**)&W2tmp, g_W2tmp);
    cudaGetSymbolAddress((void**)&W2Ts, g_W2Ts);

    cudaFuncSetAttribute(gemm_hmma, cudaFuncAttributeMaxDynamicSharedMemorySize, DSMEM1);

    const long long nBS = (long long)BS * Dd;       // 16M
    const long long dd  = (long long)Dd * Dd;       // 1M
    const long long sd  = (long long)Sq * Dd;       // 4M

    // 0) input conversion
    conv_f16v<<<(unsigned)(nBS / 4 / 256), 256>>>((const float4*)x, (__half2*)xh, nBS / 4);
    transpose_conv_f16<<<dim3(Dd / 32, Dd / 32), dim3(32, 8)>>>(Wk, WkTs, Dd, Dd);
    transpose_conv_f16<<<dim3(Dd / 32, Dd / 32), dim3(32, 8)>>>(Wv, WvTs, Dd, Dd);

    // 1) K = x@Wk + bk ; V = x@Wv + bv  -> fp16
    gemm_hmma<<<dim3(Dd / 128, BS / 128, 1), 128, DSMEM1>>>(
        xh, WkTs, bk, nullptr, Kh, Dd, Dd, 0, 0, 0, 0);
    gemm_hmma<<<dim3(Dd / 128, BS / 128, 1), 128, DSMEM1>>>(
        xh, WvTs, bv, nullptr, Vh, Dd, Dd, 0, 0, 0, 0);

    // 2) Shat_b = sum_t rfft(k_t)*rfft(v_t);  s_b = irfft(Shat_b)
    zero_S<<<(Bsz * 513 * 2 + 255) / 256, 256>>>(S, Bsz * 513 * 2);
    bind_fft<<<dim3(Sq / TOKC, Bsz), 256>>>(Kh, Vh, S);
    irfft_s<<<Bsz, 256>>>(S, s);

    // 3) r_b = bq @ M_b
    compute_r<<<dim3(Dd / 256, Bsz), 256>>>(s, bq, r);

    // 4) W2 rows via spectral unbind; transpose to [n][d]
    fft_w2<<<Dd, 256>>>(Wq, S, W2tmp);
    transpose_f16<<<dim3(Dd / 64, Dd / 64, Bsz), 256>>>(W2tmp, W2Ts, Dd, Dd, dd, dd);

    // 5) out_b = x_b @ W2_b + r_b  (fp32 out)
    gemm_hmma<<<dim3(Dd / 128, Sq / 128, Bsz), 128, DSMEM1>>>(
        xh, W2Ts, r, out, nullptr, Dd, Dd, sd, dd, Dd, sd);
}

// round 13
// speedup vs baseline: 1.1170x; 1.0812x over previous
#include <cuda_runtime.h>
#include <cuda_fp16.h>
#include <stdint.h>

#define Bsz 4
#define Sq  4096
#define Dd  1024
#define BS  (Bsz * Sq)   // 16384

// ---------------- scratch (device globals — allocation is forbidden) ----------------
__device__ __align__(256) __half g_xh[(long long)BS * Dd];
__device__ __align__(256) __half g_WkvTs[2 * Dd * Dd];               // [WkT ; WvT] rows 0..2047
__device__ __align__(256) float  g_bkv[2 * Dd];
__device__ __align__(256) __half g_KVh[(long long)BS * 2 * Dd];      // [t][ k(1024) | v(1024) ]
__device__ __align__(256) float  g_S[Bsz * 513 * 2];
__device__ __align__(256) float  g_r[Bsz * Dd];
__device__ __align__(256) __half g_W2tmp[(long long)Bsz * Dd * Dd];  // [b][d][n]
__device__ __align__(256) __half g_W2Ts[(long long)Bsz * Dd * Dd];   // [b][n][d]

// ---------------- PTX helpers ----------------
__device__ __forceinline__ uint32_t smem_u32(const void* p) {
    uint32_t a;
    asm("{ .reg .u64 t; cvta.to.shared.u64 t, %1; cvt.u32.u64 %0, t; }" : "=r"(a) : "l"(p));
    return a;
}
__device__ __forceinline__ void cp16(uint32_t dst, const void* src) {
    asm volatile("cp.async.cg.shared.global [%0], [%1], 16;" :: "r"(dst), "l"(src));
}
__device__ __forceinline__ void cp_commit() { asm volatile("cp.async.commit_group;" ::: "memory"); }
template<int N> __device__ __forceinline__ void cp_wait() {
    asm volatile("cp.async.wait_group %0;" :: "n"(N) : "memory");
}

__device__ __forceinline__ void ldsm_x4(uint32_t& r0, uint32_t& r1, uint32_t& r2, uint32_t& r3,
                                        uint32_t addr) {
    asm volatile("ldmatrix.sync.aligned.m8n8.x4.shared.b16 {%0,%1,%2,%3}, [%4];"
                 : "=r"(r0), "=r"(r1), "=r"(r2), "=r"(r3) : "r"(addr));
}
__device__ __forceinline__ void mma_fp16(float& c0, float& c1, float& c2, float& c3,
                                         uint32_t a0, uint32_t a1, uint32_t a2, uint32_t a3,
                                         uint32_t b0, uint32_t b1) {
    asm volatile(
        "mma.sync.aligned.m16n8k16.row.col.f32.f16.f16.f32 "
        "{%0,%1,%2,%3}, {%4,%5,%6,%7}, {%8,%9}, {%0,%1,%2,%3};"
        : "+f"(c0), "+f"(c1), "+f"(c2), "+f"(c3)
        : "r"(a0), "r"(a1), "r"(a2), "r"(a3), "r"(b0), "r"(b1));
}

// ---------------- fp16 HMMA GEMM: C[M,N] = Ah @ Bs^T (+bias[n]) ----------------
// CTA tile 128x128x64, 128 threads = 4 warps (2x2), warp tile 64x64, 2 CTAs/SM.
// 3-stage cp.async ring, one __syncthreads per chunk, fragment double-buffering.
#define STG1 32768
#define DSMEM1 (3 * STG1)     // 98304

__global__ __launch_bounds__(128, 2) void gemm_hmma(
    const __half* __restrict__ Ah,
    const __half* __restrict__ Bs,
    const float* __restrict__ bias, float* __restrict__ Cf,
    __half* __restrict__ Ch,
    int N, int Ktot,
    long long sA, long long sB, long long sBias, long long sC)
{
    extern __shared__ __align__(128) char smem[];
    const int tid = threadIdx.x;
    const int wid = tid >> 5, lid = tid & 31;
    const int bz = blockIdx.z;
    const long long bm = (long long)blockIdx.y * 128;
    const long long bn = (long long)blockIdx.x * 128;

    const __half* gA0 = Ah + bz * sA + bm * Ktot;
    const __half* gB = Bs + bz * sB + bn * Ktot;
    const float* biasp = bias ? bias + bz * sBias : nullptr;

    const uint32_t sb = smem_u32(smem);
    const int wm = (wid & 1) * 64;
    const int wn = (wid >> 1) * 64;

    float acc[4][8][4];
    #pragma unroll
    for (int a = 0; a < 4; a++)
        #pragma unroll
        for (int b = 0; b < 8; b++)
            #pragma unroll
            for (int c = 0; c < 4; c++) acc[a][b][c] = 0.f;

    auto load_chunk = [&](int slot, int k0) {
        const uint32_t buf = sb + slot * STG1;
        #pragma unroll
        for (int it = 0; it < 8; it++) {
            int id = tid + it * 128;
            int r = id >> 3, c = id & 7;
            cp16(buf + r * 128 + (((c ^ r) & 7) << 4),
                 gA0 + (long long)r * Ktot + k0 + c * 8);
        }
        #pragma unroll
        for (int it = 0; it < 8; it++) {
            int id = tid + it * 128;
            int r = id >> 3, c = id & 7;
            cp16(buf + 16384 + r * 128 + ((c ^ (r & 7)) << 4),
                 gB + (long long)r * Ktot + k0 + c * 8);
        }
        cp_commit();
    };

    const int nc = Ktot >> 6;        // 16
    load_chunk(0, 0);
    load_chunk(1, 64);

    const int a_row = wm + (lid & 15);
    const int a_hi  = lid >> 4;
    const int b_row = wn + (lid & 7) + ((lid >> 4) & 1) * 8;
    const int b_hi  = (lid >> 3) & 1;

    uint32_t Af[2][4][4], Bf[2][4][4];
    auto ldsm_frags = [&](uint32_t buf, int kk, uint32_t A_[4][4], uint32_t B_[4][4]) {
        #pragma unroll
        for (int mb = 0; mb < 4; mb++) {
            int r = a_row + mb * 16;
            int c = kk * 2 + a_hi;
            ldsm_x4(A_[mb][0], A_[mb][1], A_[mb][2], A_[mb][3],
                    buf + r * 128 + ((c ^ (r & 7)) << 4));
        }
        #pragma unroll
        for (int nq = 0; nq < 4; nq++) {
            int r = b_row + nq * 16;
            int c = kk * 2 + b_hi;
            ldsm_x4(B_[nq][0], B_[nq][1], B_[nq][2], B_[nq][3],
                    buf + 16384 + r * 128 + ((c ^ (r & 7)) << 4));
        }
    };

    int slot = 0;
    for (int i = 0; i < nc; i++) {
        if (i + 1 < nc) cp_wait<1>(); else cp_wait<0>();
        __syncthreads();
        if (i + 2 < nc) {
            int ns = slot + 2; if (ns >= 3) ns -= 3;
            load_chunk(ns, (i + 2) << 6);
        }
        const uint32_t buf = sb + slot * STG1;
        ldsm_frags(buf, 0, Af[0], Bf[0]);
        #pragma unroll
        for (int kk = 0; kk < 4; kk++) {
            const int cur = kk & 1;
            if (kk < 3) ldsm_frags(buf, kk + 1, Af[cur ^ 1], Bf[cur ^ 1]);
            #pragma unroll
            for (int mb = 0; mb < 4; mb++)
                #pragma unroll
                for (int nq = 0; nq < 4; nq++)
                    #pragma unroll
                    for (int half = 0; half < 2; half++) {
                        float* c = acc[mb][nq * 2 + half];
                        mma_fp16(c[0], c[1], c[2], c[3],
                                 Af[cur][mb][0], Af[cur][mb][1], Af[cur][mb][2], Af[cur][mb][3],
                                 Bf[cur][nq][half * 2], Bf[cur][nq][half * 2 + 1]);
                    }
        }
        if (++slot == 3) slot = 0;
    }

    const int er = lid >> 2;
    const int ec = (lid & 3) * 2;
    #pragma unroll
    for (int mb = 0; mb < 4; mb++) {
        #pragma unroll
        for (int nb = 0; nb < 8; nb++) {
            const float* c = acc[mb][nb];
            long long col = bn + wn + nb * 8 + ec;
            float bx = 0.f, by = 0.f;
            if (biasp) { bx = biasp[col]; by = biasp[col + 1]; }
            long long r0 = bm + wm + mb * 16 + er;
            float v0 = c[0] + bx, v1 = c[1] + by;
            float v2 = c[2] + bx, v3 = c[3] + by;
            if (Cf) {
                float* Cb = Cf + bz * sC;
                *reinterpret_cast<float2*>(Cb + r0 * N + col) = make_float2(v0, v1);
                *reinterpret_cast<float2*>(Cb + (r0 + 8) * N + col) = make_float2(v2, v3);
            } else {
                __half2 s0 = { __float2half(v0), __float2half(v1) };
                __half2 s1 = { __float2half(v2), __float2half(v3) };
                __half* Hb = Ch + bz * sC;
                *reinterpret_cast<__half2*>(Hb + r0 * N + col) = s0;
                *reinterpret_cast<__half2*>(Hb + (r0 + 8) * N + col) = s1;
            }
        }
    }
}

// ---------------- FFT machinery (radix-4 Stockham, N=1024, 256 threads) ----------------
#define FPAD(i) ((i) + ((i) >> 5))

__device__ __forceinline__ void fft1024_stages(
    float* br0, float* bi0, float* br1, float* bi1,
    const float* twr, const float* twi, int tid, int inv)
{
    float *sr = br0, *si = bi0, *dr = br1, *di = bi1;
    const int Ls[5] = {256, 64, 16, 4, 1};
    const int Ms[5] = {1, 4, 16, 64, 256};
    #pragma unroll
    for (int st = 0; st < 5; st++) {
        const int l = Ls[st], m = Ms[st];
        int j = tid / m, k = tid - j * m;
        int ti = j * (256 / l);
        float w1r = twr[ti], w1i = twi[ti];
        float w2r = w1r * w1r - w1i * w1i, w2i = 2.f * w1r * w1i;
        float w3r = w2r * w1r - w2i * w1i, w3i = w2r * w1i + w2i * w1r;
        int i0 = k + m * j;
        float c0r = sr[FPAD(i0)],             c0i = si[FPAD(i0)];
        float c1r = sr[FPAD(i0 + m * l)],     c1i = si[FPAD(i0 + m * l)];
        float c2r = sr[FPAD(i0 + 2 * m * l)], c2i = si[FPAD(i0 + 2 * m * l)];
        float c3r = sr[FPAD(i0 + 3 * m * l)], c3i = si[FPAD(i0 + 3 * m * l)];
        float t0r = c0r + c2r, t0i = c0i + c2i;
        float t1r = c0r - c2r, t1i = c0i - c2i;
        float t2r = c1r + c3r, t2i = c1i + c3i;
        float t3r = c1r - c3r, t3i = c1i - c3i;
        float u0r = t0r + t2r, u0i = t0i + t2i;
        float u2r = t0r - t2r, u2i = t0i - t2i;
        float u1r, u1i, u3r, u3i;
        if (!inv) { u1r = t1r + t3i; u1i = t1i - t3r; u3r = t1r - t3i; u3i = t1i + t3r; }
        else      { u1r = t1r - t3i; u1i = t1i + t3r; u3r = t1r + t3i; u3i = t1i - t3r; }
        int o = k + 4 * m * j;
        dr[FPAD(o)]         = u0r;                    di[FPAD(o)]         = u0i;
        dr[FPAD(o + m)]     = w1r * u1r - w1i * u1i;  di[FPAD(o + m)]     = w1r * u1i + w1i * u1r;
        dr[FPAD(o + 2 * m)] = w2r * u2r - w2i * u2i;  di[FPAD(o + 2 * m)] = w2r * u2i + w2i * u2r;
        dr[FPAD(o + 3 * m)] = w3r * u3r - w3i * u3i;  di[FPAD(o + 3 * m)] = w3r * u3i + w3i * u3r;
        __syncthreads();
        float* t;
        t = sr; sr = dr; dr = t;
        t = si; si = di; di = t;
    }
}

__device__ __forceinline__ void fft1024_stages_x2(
    float* ar0, float* ai0, float* ar1, float* ai1,
    float* br0, float* bi0, float* br1, float* bi1,
    const float* twr, const float* twi, int tid)
{
    float *sar = ar0, *sai = ai0, *dar = ar1, *dai = ai1;
    float *sbr = br0, *sbi = bi0, *dbr = br1, *dbi = bi1;
    const int Ls[5] = {256, 64, 16, 4, 1};
    const int Ms[5] = {1, 4, 16, 64, 256};
    #pragma unroll
    for (int st = 0; st < 5; st++) {
        const int l = Ls[st], m = Ms[st];
        int j = tid / m, k = tid - j * m;
        int ti = j * (256 / l);
        float w1r = twr[ti], w1i = twi[ti];
        float w2r = w1r * w1r - w1i * w1i, w2i = 2.f * w1r * w1i;
        float w3r = w2r * w1r - w2i * w1i, w3i = w2r * w1i + w2i * w1r;
        int i0 = k + m * j;
        int o = k + 4 * m * j;
        #pragma unroll
        for (int set = 0; set < 2; set++) {
            float *sr = set ? sbr : sar, *si = set ? sbi : sai;
            float *dr = set ? dbr : dar, *di = set ? dbi : dai;
            float c0r = sr[FPAD(i0)],             c0i = si[FPAD(i0)];
            float c1r = sr[FPAD(i0 + m * l)],     c1i = si[FPAD(i0 + m * l)];
            float c2r = sr[FPAD(i0 + 2 * m * l)], c2i = si[FPAD(i0 + 2 * m * l)];
            float c3r = sr[FPAD(i0 + 3 * m * l)], c3i = si[FPAD(i0 + 3 * m * l)];
            float t0r = c0r + c2r, t0i = c0i + c2i;
            float t1r = c0r - c2r, t1i = c0i - c2i;
            float t2r = c1r + c3r, t2i = c1i + c3i;
            float t3r = c1r - c3r, t3i = c1i - c3i;
            float u0r = t0r + t2r, u0i = t0i + t2i;
            float u2r = t0r - t2r, u2i = t0i - t2i;
            float u1r = t1r + t3i, u1i = t1i - t3r;
            float u3r = t1r - t3i, u3i = t1i + t3r;
            dr[FPAD(o)]         = u0r;                    di[FPAD(o)]         = u0i;
            dr[FPAD(o + m)]     = w1r * u1r - w1i * u1i;  di[FPAD(o + m)]     = w1r * u1i + w1i * u1r;
            dr[FPAD(o + 2 * m)] = w2r * u2r - w2i * u2i;  di[FPAD(o + 2 * m)] = w2r * u2i + w2i * u2r;
            dr[FPAD(o + 3 * m)] = w3r * u3r - w3i * u3i;  di[FPAD(o + 3 * m)] = w3r * u3i + w3i * u3r;
        }
        __syncthreads();
        float* t;
        t = sar; sar = dar; dar = t;  t = sai; sai = dai; dai = t;
        t = sbr; sbr = dbr; dbr = t;  t = sbi; sbi = dbi; dbi = t;
    }
}

#define TOKC 16

// bind spectrum accumulate, 2 tokens per iteration. KV packed: row = [k(1024) | v(1024)].
__global__ __launch_bounds__(256) void bind_fft(
    const __half* __restrict__ KVh, float* __restrict__ Sacc)
{
    __shared__ float Ar0[1056], Ai0[1056], Ar1[1056], Ai1[1056];
    __shared__ float Br0[1056], Bi0[1056], Br1[1056], Bi1[1056];
    __shared__ float twr[256], twi[256];
    const int tid = threadIdx.x;
    const int b = blockIdx.y;
    const long long base = ((long long)b * Sq + (long long)blockIdx.x * TOKC) * (2 * Dd);

    {
        float sv, cv;
        __sincosf(-6.28318530717958647692f * (float)tid / 1024.f, &sv, &cv);
        twr[tid] = cv; twi[tid] = sv;
    }
    float aR0 = 0.f, aI0 = 0.f, aR1 = 0.f, aI1 = 0.f, aR2 = 0.f;

    for (int tok = 0; tok < TOKC; tok += 2) {
        const __half* kv0 = KVh + base + (long long)tok * (2 * Dd);
        const __half* kv1 = kv0 + 2 * Dd;
        __syncthreads();
        #pragma unroll
        for (int q = 0; q < 4; q++) {
            int i = tid + 256 * q;
            Ar0[FPAD(i)] = __half2float(kv0[i]);
            Ai0[FPAD(i)] = __half2float(kv0[i + Dd]);
            Br0[FPAD(i)] = __half2float(kv1[i]);
            Bi0[FPAD(i)] = __half2float(kv1[i + Dd]);
        }
        __syncthreads();
        fft1024_stages_x2(Ar0, Ai0, Ar1, Ai1, Br0, Bi0, Br1, Bi1, twr, twi, tid);

        #pragma unroll
        for (int set = 0; set < 2; set++) {
            const float* Rr = set ? Br1 : Ar1;
            const float* Ri = set ? Bi1 : Ai1;
            #pragma unroll
            for (int h = 0; h < 2; h++) {
                int f = tid + h * 256;
                int nf = (1024 - f) & 1023;
                float Zr = Rr[FPAD(f)],  Zi = Ri[FPAD(f)];
                float Brv = Rr[FPAD(nf)], Biv = Ri[FPAD(nf)];
                float Kr_ = 0.5f * (Zr + Brv), Ki_ = 0.5f * (Zi - Biv);
                float Vr_ = 0.5f * (Zi + Biv), Vi_ = 0.5f * (Brv - Zr);
                float Pr = Kr_ * Vr_ - Ki_ * Vi_;
                float Pi = Kr_ * Vi_ + Ki_ * Vr_;
                if (h == 0) { aR0 += Pr; aI0 += Pi; }
                else        { aR1 += Pr; aI1 += Pi; }
            }
            if (tid == 0) {
                float Zr = Rr[FPAD(512)], Zi = Ri[FPAD(512)];
                aR2 += Zr * Zi;
            }
        }
    }
    float* Sb = Sacc + b * 513 * 2;
    atomicAdd(&Sb[tid * 2 + 0], aR0);
    atomicAdd(&Sb[tid * 2 + 1], aI0);
    atomicAdd(&Sb[(tid + 256) * 2 + 0], aR1);
    atomicAdd(&Sb[(tid + 256) * 2 + 1], aI1);
    if (tid == 0) atomicAdd(&Sb[512 * 2 + 0], aR2);
}

// W2[d][n] = iDFT( Shat_b * conj(What_d) ); CTA d < Dd: Wq row -> W2tmp (fp16).
// CTA d == Dd: row = bq -> r (fp32). (r_b = bq circ-unbind s_b, same spectral form.)
__global__ __launch_bounds__(256) void fft_w2(
    const float* __restrict__ Wq, const float* __restrict__ bq,
    const float* __restrict__ Sacc,
    __half* __restrict__ W2tmp, float* __restrict__ r)
{
    __shared__ float Ar0[1056], Ai0[1056], Ar1[1056], Ai1[1056];
    __shared__ float twf_r[256], twf_i[256], twb_r[256], twb_i[256];
    const int tid = threadIdx.x;
    const int d = blockIdx.x;
    {
        float sv, cv;
        __sincosf(-6.28318530717958647692f * (float)tid / 1024.f, &sv, &cv);
        twf_r[tid] = cv; twf_i[tid] = sv;
        twb_r[tid] = cv; twb_i[tid] = -sv;
    }
    const float* wrow = (d < Dd) ? (Wq + (long long)d * Dd) : bq;
    #pragma unroll
    for (int q = 0; q < 4; q++) {
        int i = tid + 256 * q;
        Ar0[FPAD(i)] = wrow[i];
        Ai0[FPAD(i)] = 0.f;
    }
    __syncthreads();
    fft1024_stages(Ar0, Ai0, Ar1, Ai1, twf_r, twf_i, tid, 0);

    float Wr[4], Wi[4];
    #pragma unroll
    for (int q = 0; q < 4; q++) {
        int f = tid + 256 * q;
        Wr[q] = Ar1[FPAD(f)];
        Wi[q] = Ai1[FPAD(f)];
    }

    for (int b = 0; b < Bsz; b++) {
        const float* Sb = Sacc + b * 513 * 2;
        #pragma unroll
        for (int q = 0; q < 4; q++) {
            int f = tid + 256 * q;
            float Sr, Si;
            if (f <= 512) { Sr = Sb[f * 2]; Si = Sb[f * 2 + 1]; }
            else          { Sr = Sb[(1024 - f) * 2]; Si = -Sb[(1024 - f) * 2 + 1]; }
            Ar0[FPAD(f)] = Sr * Wr[q] + Si * Wi[q];
            Ai0[FPAD(f)] = Si * Wr[q] - Sr * Wi[q];
        }
        __syncthreads();
        fft1024_stages(Ar0, Ai0, Ar1, Ai1, twb_r, twb_i, tid, 1);
        if (d < Dd) {
            __half* dst = W2tmp + ((long long)b << 20) + ((long long)d << 10);
            #pragma unroll
            for (int q = 0; q < 4; q++) {
                int i = tid + 256 * q;
                dst[i] = __float2half(Ar1[FPAD(i)] * (1.f / 1024.f));
            }
        } else {
            float* dst = r + b * Dd;
            #pragma unroll
            for (int q = 0; q < 4; q++) {
                int i = tid + 256 * q;
                dst[i] = Ar1[FPAD(i)] * (1.f / 1024.f);
            }
        }
    }
}

// ---------------- prep kernels ----------------
__global__ void zero_S(float* p, int n)
{
    int i = blockIdx.x * 256 + threadIdx.x;
    if (i < n) p[i] = 0.f;
}

__global__ void conv_f16v(const float4* __restrict__ x, __half2* __restrict__ h, long long n4)
{
    long long i = (long long)blockIdx.x * blockDim.x + threadIdx.x;
    if (i < n4) {
        float4 v = x[i];
        h[i * 2 + 0] = __half2{__float2half(v.x), __float2half(v.y)};
        h[i * 2 + 1] = __half2{__float2half(v.z), __float2half(v.w)};
    }
}

__global__ void transpose_conv_f16(const float* __restrict__ src, __half* __restrict__ dst,
                                   int R, int C)
{
    __shared__ float t[32][33];
    int c0 = blockIdx.x * 32, r0 = blockIdx.y * 32;
    int tx = threadIdx.x, ty = threadIdx.y;
    #pragma unroll
    for (int k = 0; k < 32; k += 8)
        t[ty + k][tx] = src[(long long)(r0 + ty + k) * C + c0 + tx];
    __syncthreads();
    #pragma unroll
    for (int k = 0; k < 32; k += 8)
        dst[(long long)(c0 + ty + k) * R + r0 + tx] = __float2half(t[tx][ty + k]);
}

__global__ void concat_bias(const float* __restrict__ bk, const float* __restrict__ bv,
                            float* __restrict__ bkv)
{
    int i = blockIdx.x * 256 + threadIdx.x;
    if (i < Dd) bkv[i] = bk[i];
    else if (i < 2 * Dd) bkv[i] = bv[i - Dd];
}

__global__ void transpose_f16(const __half* __restrict__ s, __half* __restrict__ d,
                              int R, int C, long long sIn, long long sOut)
{
    __shared__ __half t[64][65];
    int b = blockIdx.z;
    s += (long long)b * sIn; d += (long long)b * sOut;
    int c0 = blockIdx.x * 64, r0 = blockIdx.y * 64;
    int tid = threadIdx.x;
    #pragma unroll
    for (int it = 0; it < 8; it++) {
        int id = tid + it * 256;
        int row = id >> 5, cp = (id & 31) * 2;
        __half2 v = *reinterpret_cast<const __half2*>(s + (long long)(r0 + row) * C + c0 + cp);
        t[row][cp] = v.x; t[row][cp + 1] = v.y;
    }
    __syncthreads();
    #pragma unroll
    for (int it = 0; it < 8; it++) {
        int id = tid + it * 256;
        int cc = id >> 5, rp = (id & 31) * 2;
        __half2 v = { t[rp][cc], t[rp + 1][cc] };
        *reinterpret_cast<__half2*>(d + (long long)(c0 + cc) * R + r0 + rp) = v;
    }
}

// ---------------- launcher ----------------
extern "C" void kernel_launch(void* const* d_in, const int* in_sizes, int n_in,
                              void* d_out, int out_size)
{
    const float* x  = (const float*)d_in[0];
    const float* Wq = (const float*)d_in[1];
    const float* bq = (const float*)d_in[2];
    const float* Wk = (const float*)d_in[3];
    const float* bk = (const float*)d_in[4];
    const float* Wv = (const float*)d_in[5];
    const float* bv = (const float*)d_in[6];
    float* out = (float*)d_out;

    __half *xh, *WkvTs, *KVh, *W2tmp, *W2Ts;
    float *bkv, *S, *r;
    cudaGetSymbolAddress((void**)&xh, g_xh);
    cudaGetSymbolAddress((void**)&WkvTs, g_WkvTs);
    cudaGetSymbolAddress((void**)&bkv, g_bkv);
    cudaGetSymbolAddress((void**)&KVh, g_KVh);
    cudaGetSymbolAddress((void**)&S, g_S);
    cudaGetSymbolAddress((void**)&r, g_r);
    cudaGetSymbolAddress((void**)&W2tmp, g_W2tmp);
    cudaGetSymbolAddress((void**)&W2Ts, g_W2Ts);

    cudaFuncSetAttribute(gemm_hmma, cudaFuncAttributeMaxDynamicSharedMemorySize, DSMEM1);

    const long long nBS = (long long)BS * Dd;       // 16M
    const long long dd  = (long long)Dd * Dd;       // 1M
    const long long sd  = (long long)Sq * Dd;       // 4M

    // 0) input conversion: x -> fp16; [WkT ; WvT] concat; [bk ; bv] concat
    conv_f16v<<<(unsigned)(nBS / 4 / 256), 256>>>((const float4*)x, (__half2*)xh, nBS / 4);
    transpose_conv_f16<<<dim3(Dd / 32, Dd / 32), dim3(32, 8)>>>(Wk, WkvTs, Dd, Dd);
    transpose_conv_f16<<<dim3(Dd / 32, Dd / 32), dim3(32, 8)>>>(Wv, WkvTs + dd, Dd, Dd);
    concat_bias<<<(2 * Dd) / 256, 256>>>(bk, bv, bkv);

    // 1) [K|V] = x @ [Wk|Wv] + [bk|bv]  -> fp16, one fused launch (N=2048)
    gemm_hmma<<<dim3(2 * Dd / 128, BS / 128, 1), 128, DSMEM1>>>(
        xh, WkvTs, bkv, nullptr, KVh, 2 * Dd, Dd, 0, 0, 0, 0);

    // 2) Shat_b = sum_t rfft(k_t)*rfft(v_t)
    zero_S<<<(Bsz * 513 * 2 + 255) / 256, 256>>>(S, Bsz * 513 * 2);
    bind_fft<<<dim3(Sq / TOKC, Bsz), 256>>>(KVh, S);

    // 3) W2 rows (d<Dd) + r (d==Dd) via spectral unbind; transpose W2 to [n][d]
    fft_w2<<<Dd + 1, 256>>>(Wq, bq, S, W2tmp, r);
    transpose_f16<<<dim3(Dd / 64, Dd / 64, Bsz), 256>>>(W2tmp, W2Ts, Dd, Dd, dd, dd);

    // 4) out_b = x_b @ W2_b + r_b  (fp32 out)
    gemm_hmma<<<dim3(Dd / 128, Sq / 128, Bsz), 128, DSMEM1>>>(
        xh, W2Ts, r, out, nullptr, Dd, Dd, sd, dd, Dd, sd);
}